// round 9
// baseline (speedup 1.0000x reference)
#include <cuda_runtime.h>
#include <mma.h>
#include <math.h>

using namespace nvcuda;

#define N_NODES 50000
#define N_EDGES 800000
#define FDIM 128
#define CAP   64          // max in-degree capacity (Poisson(16): P(>=64) ~ 1e-19)
#define GM    64          // GEMM rows per block
#define GLD   132         // smem leading dim in floats (128 + 4 pad, 16B-mult)

// Scratch (allocation-free)
__device__ int   g_cnt[N_NODES];                 // in-degree counters
__device__ int   g_src_list[N_NODES * CAP];      // inverse adjacency
__device__ float g_Wt[FDIM * FDIM];              // Wt[k][c] = W[c][k]
__device__ float g_agg[N_NODES * FDIM];          // gathered features (L2-resident)

// ---------------------------------------------------------------------------
// K1: zero counters + transpose W.
// ---------------------------------------------------------------------------
__global__ void prep_kernel(const float* __restrict__ W) {
    int i = blockIdx.x * blockDim.x + threadIdx.x;
    if (i < N_NODES) g_cnt[i] = 0;
    if (i < FDIM * FDIM) {
        int k = i >> 7;
        int c = i & 127;
        g_Wt[i] = W[c * FDIM + k];
    }
}

// ---------------------------------------------------------------------------
// K2: build inverse adjacency lists (int atomics only).
// ---------------------------------------------------------------------------
__global__ void build_lists_kernel(const int* __restrict__ src,
                                   const int* __restrict__ dst) {
    int e = blockIdx.x * blockDim.x + threadIdx.x;
    if (e >= N_EDGES) return;
    int d = dst[e];
    int slot = atomicAdd(&g_cnt[d], 1);
    if (slot < CAP) g_src_list[d * CAP + slot] = src[e];
}

// ---------------------------------------------------------------------------
// K3: gather. One WARP per row; shfl-broadcast src list; MLP=4.
//   agg[row] = norm[row] * sum_s feat[s]*norm[s]
// ---------------------------------------------------------------------------
__global__ void __launch_bounds__(256)
gather_kernel(const float* __restrict__ feat,
              const float* __restrict__ norm) {
    const int warp = threadIdx.x >> 5;
    const int lane = threadIdx.x & 31;
    const int row  = blockIdx.x * 8 + warp;
    if (row >= N_NODES) return;

    int deg = g_cnt[row];
    if (deg > CAP) deg = CAP;
    const int* lst = g_src_list + row * CAP;
    const float4* feat4 = reinterpret_cast<const float4*>(feat);

    float4 a0 = make_float4(0.f, 0.f, 0.f, 0.f);
    float4 a1 = a0, a2 = a0, a3 = a0;

    for (int base = 0; base < deg; base += 32) {
        int cn = deg - base; if (cn > 32) cn = 32;
        int   sid = (lane < cn) ? lst[base + lane] : 0;
        float nn  = (lane < cn) ? __ldg(norm + sid) : 0.f;

        int j = 0;
        for (; j + 3 < cn; j += 4) {
            int   s0 = __shfl_sync(0xffffffffu, sid, j + 0);
            int   s1 = __shfl_sync(0xffffffffu, sid, j + 1);
            int   s2 = __shfl_sync(0xffffffffu, sid, j + 2);
            int   s3 = __shfl_sync(0xffffffffu, sid, j + 3);
            float n0 = __shfl_sync(0xffffffffu, nn, j + 0);
            float n1 = __shfl_sync(0xffffffffu, nn, j + 1);
            float n2 = __shfl_sync(0xffffffffu, nn, j + 2);
            float n3 = __shfl_sync(0xffffffffu, nn, j + 3);
            float4 f0 = feat4[(size_t)s0 * 32 + lane];
            float4 f1 = feat4[(size_t)s1 * 32 + lane];
            float4 f2 = feat4[(size_t)s2 * 32 + lane];
            float4 f3 = feat4[(size_t)s3 * 32 + lane];
            a0.x = fmaf(f0.x, n0, a0.x); a0.y = fmaf(f0.y, n0, a0.y);
            a0.z = fmaf(f0.z, n0, a0.z); a0.w = fmaf(f0.w, n0, a0.w);
            a1.x = fmaf(f1.x, n1, a1.x); a1.y = fmaf(f1.y, n1, a1.y);
            a1.z = fmaf(f1.z, n1, a1.z); a1.w = fmaf(f1.w, n1, a1.w);
            a2.x = fmaf(f2.x, n2, a2.x); a2.y = fmaf(f2.y, n2, a2.y);
            a2.z = fmaf(f2.z, n2, a2.z); a2.w = fmaf(f2.w, n2, a2.w);
            a3.x = fmaf(f3.x, n3, a3.x); a3.y = fmaf(f3.y, n3, a3.y);
            a3.z = fmaf(f3.z, n3, a3.z); a3.w = fmaf(f3.w, n3, a3.w);
        }
        for (; j < cn; j++) {
            int   s0 = __shfl_sync(0xffffffffu, sid, j);
            float n0 = __shfl_sync(0xffffffffu, nn, j);
            float4 f0 = feat4[(size_t)s0 * 32 + lane];
            a0.x = fmaf(f0.x, n0, a0.x); a0.y = fmaf(f0.y, n0, a0.y);
            a0.z = fmaf(f0.z, n0, a0.z); a0.w = fmaf(f0.w, n0, a0.w);
        }
    }

    float nd = __ldg(norm + row);
    float4 o;
    o.x = (a0.x + a1.x + a2.x + a3.x) * nd;
    o.y = (a0.y + a1.y + a2.y + a3.y) * nd;
    o.z = (a0.z + a1.z + a2.z + a3.z) * nd;
    o.w = (a0.w + a1.w + a2.w + a3.w) * nd;
    reinterpret_cast<float4*>(g_agg)[(size_t)row * 32 + lane] = o;
}

// ---------------------------------------------------------------------------
// K4: out = tanh(agg @ Wt + b) via TF32 WMMA with 3xTF32 compensation.
// Block: 64 rows x 128 cols, 256 thr = 8 warps (4 row-warps x 2 col-warps).
// Warp: 16 rows x 64 cols = 4 m16n16k8 column tiles.
// acc += big_a*big_b + small_a*big_b + big_a*small_b  (error ~2^-22)
// smem: As 64*132*4 = 33,792B + Bs 128*132*4 = 67,584B = 101,376B -> 2 CTA/SM.
// Epilogue: C frags -> smem (reuse As) -> bias + tanh -> coalesced store.
// ---------------------------------------------------------------------------
__global__ void __launch_bounds__(256, 2)
gemm_tanh_tc_kernel(const float* __restrict__ bias_in,
                    float* __restrict__ out) {
    extern __shared__ float sh[];
    float* As = sh;                 // [GM][GLD]
    float* Bs = sh + GM * GLD;      // [FDIM][GLD]

    const int t    = threadIdx.x;       // 0..255
    const int wid  = t >> 5;            // 0..7
    const int wr   = wid >> 1;          // row-warp 0..3 -> rows wr*16
    const int wc   = wid & 1;           // col-warp 0..1 -> cols wc*64
    const int row0 = blockIdx.x * GM;

    // stage Wt -> Bs
    {
        const float4* Wt4 = reinterpret_cast<const float4*>(g_Wt);
        #pragma unroll
        for (int i = t; i < FDIM * 32; i += 256) {
            int k = i >> 5, c4 = i & 31;
            *reinterpret_cast<float4*>(Bs + k * GLD + c4 * 4) = Wt4[k * 32 + c4];
        }
    }
    // stage agg -> As (zero-pad tail rows)
    {
        const float4* agg4 = reinterpret_cast<const float4*>(g_agg);
        #pragma unroll
        for (int i = t; i < GM * 32; i += 256) {
            int r = i >> 5, c4 = i & 31;
            int row = row0 + r;
            float4 v = (row < N_NODES) ? agg4[(size_t)row * 32 + c4]
                                       : make_float4(0.f, 0.f, 0.f, 0.f);
            *reinterpret_cast<float4*>(As + r * GLD + c4 * 4) = v;
        }
    }
    __syncthreads();

    wmma::fragment<wmma::accumulator, 16, 16, 8, float> acc[4];
    #pragma unroll
    for (int c = 0; c < 4; c++) wmma::fill_fragment(acc[c], 0.0f);

    #pragma unroll
    for (int k = 0; k < FDIM; k += 8) {
        wmma::fragment<wmma::matrix_a, 16, 16, 8, wmma::precision::tf32,
                       wmma::row_major> a_big, a_small;
        wmma::load_matrix_sync(a_big, As + (wr * 16) * GLD + k, GLD);
        #pragma unroll
        for (int i = 0; i < a_big.num_elements; i++) {
            float v = a_big.x[i];
            float bg = wmma::__float_to_tf32(v);
            a_big.x[i]   = bg;
            a_small.x[i] = wmma::__float_to_tf32(v - bg);
        }
        #pragma unroll
        for (int c = 0; c < 4; c++) {
            wmma::fragment<wmma::matrix_b, 16, 16, 8, wmma::precision::tf32,
                           wmma::row_major> b_big, b_small;
            wmma::load_matrix_sync(b_big, Bs + k * GLD + wc * 64 + c * 16, GLD);
            #pragma unroll
            for (int i = 0; i < b_big.num_elements; i++) {
                float v = b_big.x[i];
                float bg = wmma::__float_to_tf32(v);
                b_big.x[i]   = bg;
                b_small.x[i] = wmma::__float_to_tf32(v - bg);
            }
            wmma::mma_sync(acc[c], a_small, b_big, acc[c]);
            wmma::mma_sync(acc[c], a_big, b_small, acc[c]);
            wmma::mma_sync(acc[c], a_big, b_big, acc[c]);
        }
    }

    __syncthreads();   // all warps done reading As before reuse as C buffer
    float* Cs = As;    // [GM][GLD], 64x128 used
    #pragma unroll
    for (int c = 0; c < 4; c++)
        wmma::store_matrix_sync(Cs + (wr * 16) * GLD + wc * 64 + c * 16,
                                acc[c], GLD, wmma::mem_row_major);
    __syncthreads();

    // epilogue: bias + tanh + coalesced float4 store
    {
        const float4* b4 = reinterpret_cast<const float4*>(bias_in);
        #pragma unroll
        for (int i = t; i < GM * 32; i += 256) {
            int r = i >> 5, c4 = i & 31;
            int row = row0 + r;
            if (row < N_NODES) {
                float4 v = *reinterpret_cast<float4*>(Cs + r * GLD + c4 * 4);
                float4 bb = b4[c4];
                float4 o;
                o.x = tanhf(v.x + bb.x);
                o.y = tanhf(v.y + bb.y);
                o.z = tanhf(v.z + bb.z);
                o.w = tanhf(v.w + bb.w);
                reinterpret_cast<float4*>(out)[(size_t)row * 32 + c4] = o;
            }
        }
    }
}

// ---------------------------------------------------------------------------
// Launch. Inputs: features, norm, W, b, src, dst. Output float [N, 128].
// ---------------------------------------------------------------------------
extern "C" void kernel_launch(void* const* d_in, const int* in_sizes, int n_in,
                              void* d_out, int out_size) {
    const float* feat = (const float*)d_in[0];
    const float* norm = (const float*)d_in[1];
    const float* W    = (const float*)d_in[2];
    const float* b    = (const float*)d_in[3];
    const int*   src  = (const int*)d_in[4];
    const int*   dst  = (const int*)d_in[5];
    float* out = (float*)d_out;

    prep_kernel<<<(N_NODES + 255) / 256, 256>>>(W);
    build_lists_kernel<<<(N_EDGES + 255) / 256, 256>>>(src, dst);
    gather_kernel<<<(N_NODES + 7) / 8, 256>>>(feat, norm);

    int smem = (GM + FDIM) * GLD * (int)sizeof(float);   // 101,376 B
    cudaFuncSetAttribute(gemm_tanh_tc_kernel,
                         cudaFuncAttributeMaxDynamicSharedMemorySize, smem);
    gemm_tanh_tc_kernel<<<(N_NODES + GM - 1) / GM, 256, smem>>>(b, out);
}

// round 10
// speedup vs baseline: 1.2405x; 1.2405x over previous
#include <cuda_runtime.h>
#include <cuda_fp16.h>
#include <math.h>

#define N_NODES 50000
#define N_EDGES 800000
#define FDIM 128
#define CAP   64          // max in-degree capacity (Poisson(16): P(>=64) ~ 1e-19)
#define TM    64          // GEMM rows per block
#define ASTRIDE 33        // As row stride in float4 (32 data + 1 pad)

// Scratch (allocation-free)
__device__ int    g_cnt[N_NODES];                // in-degree counters
__device__ int    g_src_list[N_NODES * CAP];     // inverse adjacency
__device__ float  g_Wt[FDIM * FDIM];             // Wt[k][c] = W[c][k]
__device__ float  g_agg[N_NODES * FDIM];         // gathered features (fp32)
__device__ __half g_feat_h[N_NODES * FDIM];      // fp16 features (halved traffic)

// ---------------------------------------------------------------------------
// K1: zero counters + transpose W + convert features to fp16.
// Grid covers N_NODES*FDIM/4 threads (largest job).
// ---------------------------------------------------------------------------
__global__ void prep_kernel(const float* __restrict__ W,
                            const float* __restrict__ feat) {
    int i = blockIdx.x * blockDim.x + threadIdx.x;
    if (i < N_NODES) g_cnt[i] = 0;
    if (i < FDIM * FDIM) {
        int k = i >> 7;
        int c = i & 127;
        g_Wt[i] = W[c * FDIM + k];
    }
    if (i < N_NODES * FDIM / 4) {
        float4 v = reinterpret_cast<const float4*>(feat)[i];
        __half2 h0 = __floats2half2_rn(v.x, v.y);
        __half2 h1 = __floats2half2_rn(v.z, v.w);
        uint2 u;
        u.x = *reinterpret_cast<unsigned*>(&h0);
        u.y = *reinterpret_cast<unsigned*>(&h1);
        reinterpret_cast<uint2*>(g_feat_h)[i] = u;
    }
}

// ---------------------------------------------------------------------------
// K2: build inverse adjacency lists (int atomics only).
// ---------------------------------------------------------------------------
__global__ void build_lists_kernel(const int* __restrict__ src,
                                   const int* __restrict__ dst) {
    int e = blockIdx.x * blockDim.x + threadIdx.x;
    if (e >= N_EDGES) return;
    int d = dst[e];
    int slot = atomicAdd(&g_cnt[d], 1);
    if (slot < CAP) g_src_list[d * CAP + slot] = src[e];
}

// ---------------------------------------------------------------------------
// K3: gather. One WARP per row; shfl-broadcast src list; fp16 feature loads
// (8 B/edge/lane instead of 16 B) with fp32 accumulation; MLP=4.
//   agg[row] = norm[row] * sum_s feat[s]*norm[s]
// ---------------------------------------------------------------------------
__global__ void __launch_bounds__(256)
gather_kernel(const float* __restrict__ norm) {
    const int warp = threadIdx.x >> 5;
    const int lane = threadIdx.x & 31;
    const int row  = blockIdx.x * 8 + warp;
    if (row >= N_NODES) return;

    int deg = g_cnt[row];
    if (deg > CAP) deg = CAP;
    const int* lst = g_src_list + row * CAP;
    const uint2* feat_h2 = reinterpret_cast<const uint2*>(g_feat_h);

    float4 a0 = make_float4(0.f, 0.f, 0.f, 0.f);
    float4 a1 = a0, a2 = a0, a3 = a0;

    for (int base = 0; base < deg; base += 32) {
        int cn = deg - base; if (cn > 32) cn = 32;
        int   sid = (lane < cn) ? lst[base + lane] : 0;
        float nn  = (lane < cn) ? __ldg(norm + sid) : 0.f;

        int j = 0;
        for (; j + 3 < cn; j += 4) {
            int   s0 = __shfl_sync(0xffffffffu, sid, j + 0);
            int   s1 = __shfl_sync(0xffffffffu, sid, j + 1);
            int   s2 = __shfl_sync(0xffffffffu, sid, j + 2);
            int   s3 = __shfl_sync(0xffffffffu, sid, j + 3);
            float n0 = __shfl_sync(0xffffffffu, nn, j + 0);
            float n1 = __shfl_sync(0xffffffffu, nn, j + 1);
            float n2 = __shfl_sync(0xffffffffu, nn, j + 2);
            float n3 = __shfl_sync(0xffffffffu, nn, j + 3);
            uint2 u0 = feat_h2[(size_t)s0 * 32 + lane];
            uint2 u1 = feat_h2[(size_t)s1 * 32 + lane];
            uint2 u2 = feat_h2[(size_t)s2 * 32 + lane];
            uint2 u3 = feat_h2[(size_t)s3 * 32 + lane];
            float2 f0a = __half22float2(*reinterpret_cast<__half2*>(&u0.x));
            float2 f0b = __half22float2(*reinterpret_cast<__half2*>(&u0.y));
            float2 f1a = __half22float2(*reinterpret_cast<__half2*>(&u1.x));
            float2 f1b = __half22float2(*reinterpret_cast<__half2*>(&u1.y));
            float2 f2a = __half22float2(*reinterpret_cast<__half2*>(&u2.x));
            float2 f2b = __half22float2(*reinterpret_cast<__half2*>(&u2.y));
            float2 f3a = __half22float2(*reinterpret_cast<__half2*>(&u3.x));
            float2 f3b = __half22float2(*reinterpret_cast<__half2*>(&u3.y));
            a0.x = fmaf(f0a.x, n0, a0.x); a0.y = fmaf(f0a.y, n0, a0.y);
            a0.z = fmaf(f0b.x, n0, a0.z); a0.w = fmaf(f0b.y, n0, a0.w);
            a1.x = fmaf(f1a.x, n1, a1.x); a1.y = fmaf(f1a.y, n1, a1.y);
            a1.z = fmaf(f1b.x, n1, a1.z); a1.w = fmaf(f1b.y, n1, a1.w);
            a2.x = fmaf(f2a.x, n2, a2.x); a2.y = fmaf(f2a.y, n2, a2.y);
            a2.z = fmaf(f2b.x, n2, a2.z); a2.w = fmaf(f2b.y, n2, a2.w);
            a3.x = fmaf(f3a.x, n3, a3.x); a3.y = fmaf(f3a.y, n3, a3.y);
            a3.z = fmaf(f3b.x, n3, a3.z); a3.w = fmaf(f3b.y, n3, a3.w);
        }
        for (; j < cn; j++) {
            int   s0 = __shfl_sync(0xffffffffu, sid, j);
            float n0 = __shfl_sync(0xffffffffu, nn, j);
            uint2 u0 = feat_h2[(size_t)s0 * 32 + lane];
            float2 f0a = __half22float2(*reinterpret_cast<__half2*>(&u0.x));
            float2 f0b = __half22float2(*reinterpret_cast<__half2*>(&u0.y));
            a0.x = fmaf(f0a.x, n0, a0.x); a0.y = fmaf(f0a.y, n0, a0.y);
            a0.z = fmaf(f0b.x, n0, a0.z); a0.w = fmaf(f0b.y, n0, a0.w);
        }
    }

    float nd = __ldg(norm + row);
    float4 o;
    o.x = (a0.x + a1.x + a2.x + a3.x) * nd;
    o.y = (a0.y + a1.y + a2.y + a3.y) * nd;
    o.z = (a0.z + a1.z + a2.z + a3.z) * nd;
    o.w = (a0.w + a1.w + a2.w + a3.w) * nd;
    reinterpret_cast<float4*>(g_agg)[(size_t)row * 32 + lane] = o;
}

// ---------------------------------------------------------------------------
// K4: out = tanh(agg @ Wt + b). EXACT R6 config (measured 52.3us).
// 256 threads = 8 warps. Warp w covers 64 rows x cols [w*16, w*16+16).
// Lane: rb = lane>>2 (base row), cq = w*4 + (lane&3) (col-chunk).
// Thread micro-tile 8x4; B-load and A-load both 1-phase LDS.128.
// smem: As 33,792B + Bs 65,536B = 99,328B -> 2 CTA/SM.
// ---------------------------------------------------------------------------
__global__ void __launch_bounds__(256, 2)
gemm_tanh_kernel(const float* __restrict__ b,
                 float* __restrict__ out) {
    extern __shared__ float sh[];
    float* As = sh;                        // [TM][ASTRIDE*4] floats (padded)
    float* Bs = sh + TM * ASTRIDE * 4;     // [FDIM][FDIM] : Bs[k][c]

    const int t    = threadIdx.x;          // 0..255
    const int wid  = t >> 5;               // warp 0..7 -> col slice
    const int lane = t & 31;
    const int rb   = lane >> 2;            // base row 0..7
    const int cq   = wid * 4 + (lane & 3); // col-chunk index (float4) 0..31
    const int row0 = blockIdx.x * TM;

    {
        float4* Bs4 = reinterpret_cast<float4*>(Bs);
        const float4* Wt4 = reinterpret_cast<const float4*>(g_Wt);
        #pragma unroll
        for (int i = t; i < FDIM * FDIM / 4; i += 256) Bs4[i] = Wt4[i];
    }
    {
        float4* As4 = reinterpret_cast<float4*>(As);
        const float4* agg4 = reinterpret_cast<const float4*>(g_agg);
        #pragma unroll
        for (int i = t; i < TM * 32; i += 256) {
            int r = i >> 5, c4 = i & 31;
            int row = row0 + r;
            As4[r * ASTRIDE + c4] = (row < N_NODES)
                ? agg4[(size_t)row * 32 + c4]
                : make_float4(0.f, 0.f, 0.f, 0.f);
        }
    }
    __syncthreads();

    float acc[8][4];
    #pragma unroll
    for (int r = 0; r < 8; r++)
        #pragma unroll
        for (int c = 0; c < 4; c++) acc[r][c] = 0.f;

    const float4* Bs4 = reinterpret_cast<const float4*>(Bs);
    const float4* As4 = reinterpret_cast<const float4*>(As);

    #pragma unroll 4
    for (int k4 = 0; k4 < FDIM / 4; k4++) {
        float4 b0 = Bs4[(k4 * 4 + 0) * 32 + cq];
        float4 b1 = Bs4[(k4 * 4 + 1) * 32 + cq];
        float4 b2 = Bs4[(k4 * 4 + 2) * 32 + cq];
        float4 b3 = Bs4[(k4 * 4 + 3) * 32 + cq];
        #pragma unroll
        for (int r = 0; r < 8; r++) {
            float4 a = As4[(rb + 8 * r) * ASTRIDE + k4];  // 1-phase LDS.128
            acc[r][0] = fmaf(a.x, b0.x, acc[r][0]);
            acc[r][1] = fmaf(a.x, b0.y, acc[r][1]);
            acc[r][2] = fmaf(a.x, b0.z, acc[r][2]);
            acc[r][3] = fmaf(a.x, b0.w, acc[r][3]);
            acc[r][0] = fmaf(a.y, b1.x, acc[r][0]);
            acc[r][1] = fmaf(a.y, b1.y, acc[r][1]);
            acc[r][2] = fmaf(a.y, b1.z, acc[r][2]);
            acc[r][3] = fmaf(a.y, b1.w, acc[r][3]);
            acc[r][0] = fmaf(a.z, b2.x, acc[r][0]);
            acc[r][1] = fmaf(a.z, b2.y, acc[r][1]);
            acc[r][2] = fmaf(a.z, b2.z, acc[r][2]);
            acc[r][3] = fmaf(a.z, b2.w, acc[r][3]);
            acc[r][0] = fmaf(a.w, b3.x, acc[r][0]);
            acc[r][1] = fmaf(a.w, b3.y, acc[r][1]);
            acc[r][2] = fmaf(a.w, b3.z, acc[r][2]);
            acc[r][3] = fmaf(a.w, b3.w, acc[r][3]);
        }
    }

    float4 bias = reinterpret_cast<const float4*>(b)[cq];
    #pragma unroll
    for (int r = 0; r < 8; r++) {
        int row = row0 + rb + 8 * r;
        if (row < N_NODES) {
            float4 o;
            o.x = tanhf(acc[r][0] + bias.x);
            o.y = tanhf(acc[r][1] + bias.y);
            o.z = tanhf(acc[r][2] + bias.z);
            o.w = tanhf(acc[r][3] + bias.w);
            reinterpret_cast<float4*>(out + (size_t)row * FDIM)[cq] = o;
        }
    }
}

// ---------------------------------------------------------------------------
// Launch. Inputs: features, norm, W, b, src, dst. Output float [N, 128].
// ---------------------------------------------------------------------------
extern "C" void kernel_launch(void* const* d_in, const int* in_sizes, int n_in,
                              void* d_out, int out_size) {
    const float* feat = (const float*)d_in[0];
    const float* norm = (const float*)d_in[1];
    const float* W    = (const float*)d_in[2];
    const float* b    = (const float*)d_in[3];
    const int*   src  = (const int*)d_in[4];
    const int*   dst  = (const int*)d_in[5];
    float* out = (float*)d_out;

    int prep_threads = N_NODES * FDIM / 4;   // 1.6M (covers all three jobs)
    prep_kernel<<<(prep_threads + 255) / 256, 256>>>(W, feat);
    build_lists_kernel<<<(N_EDGES + 255) / 256, 256>>>(src, dst);
    gather_kernel<<<(N_NODES + 7) / 8, 256>>>(norm);

    int smem = (TM * ASTRIDE * 4 + FDIM * FDIM) * (int)sizeof(float);  // 99,328 B
    cudaFuncSetAttribute(gemm_tanh_kernel,
                         cudaFuncAttributeMaxDynamicSharedMemorySize, smem);
    gemm_tanh_kernel<<<(N_NODES + TM - 1) / TM, 256, smem>>>(b, out);
}

// round 11
// speedup vs baseline: 1.9294x; 1.5553x over previous
#include <cuda_runtime.h>
#include <cuda_fp16.h>
#include <mma.h>
#include <math.h>

using namespace nvcuda;

#define N_NODES 50000
#define N_EDGES 800000
#define FDIM 128
#define CAP   64          // max in-degree capacity (Poisson(16): P(>=64) ~ 1e-19)
#define GM    64          // GEMM rows per block
#define ALD   136         // smem leading dim in halves (128 + 8 pad; 272B rows, 16B-mult)
#define CLD   132         // epilogue float leading dim

// Scratch (allocation-free)
__device__ int    g_cnt[N_NODES];                // in-degree counters
__device__ int    g_src_list[N_NODES * CAP];     // inverse adjacency
__device__ __half g_Wt_h[FDIM * FDIM];           // Wt_h[k*128+c] = (half)W[c][k]
__device__ __half g_agg_h[N_NODES * FDIM];       // gathered features, fp16

// ---------------------------------------------------------------------------
// K1: zero counters + transpose W -> fp16.
// ---------------------------------------------------------------------------
__global__ void prep_kernel(const float* __restrict__ W) {
    int i = blockIdx.x * blockDim.x + threadIdx.x;
    if (i < N_NODES) g_cnt[i] = 0;
    if (i < FDIM * FDIM) {
        int k = i >> 7;
        int c = i & 127;
        g_Wt_h[i] = __float2half_rn(W[c * FDIM + k]);
    }
}

// ---------------------------------------------------------------------------
// K2: build inverse adjacency lists (int atomics only).
// ---------------------------------------------------------------------------
__global__ void build_lists_kernel(const int* __restrict__ src,
                                   const int* __restrict__ dst) {
    int e = blockIdx.x * blockDim.x + threadIdx.x;
    if (e >= N_EDGES) return;
    int d = dst[e];
    int slot = atomicAdd(&g_cnt[d], 1);
    if (slot < CAP) g_src_list[d * CAP + slot] = src[e];
}

// ---------------------------------------------------------------------------
// K3: gather (R6-proven fp32 path). One WARP per row; shfl-broadcast lists;
// MLP=4. Epilogue converts to fp16 (halves the store traffic).
//   agg[row] = norm[row] * sum_s feat[s]*norm[s]
// ---------------------------------------------------------------------------
__global__ void __launch_bounds__(256)
gather_kernel(const float* __restrict__ feat,
              const float* __restrict__ norm) {
    const int warp = threadIdx.x >> 5;
    const int lane = threadIdx.x & 31;
    const int row  = blockIdx.x * 8 + warp;
    if (row >= N_NODES) return;

    int deg = g_cnt[row];
    if (deg > CAP) deg = CAP;
    const int* lst = g_src_list + row * CAP;
    const float4* feat4 = reinterpret_cast<const float4*>(feat);

    float4 a0 = make_float4(0.f, 0.f, 0.f, 0.f);
    float4 a1 = a0, a2 = a0, a3 = a0;

    for (int base = 0; base < deg; base += 32) {
        int cn = deg - base; if (cn > 32) cn = 32;
        int   sid = (lane < cn) ? lst[base + lane] : 0;
        float nn  = (lane < cn) ? __ldg(norm + sid) : 0.f;

        int j = 0;
        for (; j + 3 < cn; j += 4) {
            int   s0 = __shfl_sync(0xffffffffu, sid, j + 0);
            int   s1 = __shfl_sync(0xffffffffu, sid, j + 1);
            int   s2 = __shfl_sync(0xffffffffu, sid, j + 2);
            int   s3 = __shfl_sync(0xffffffffu, sid, j + 3);
            float n0 = __shfl_sync(0xffffffffu, nn, j + 0);
            float n1 = __shfl_sync(0xffffffffu, nn, j + 1);
            float n2 = __shfl_sync(0xffffffffu, nn, j + 2);
            float n3 = __shfl_sync(0xffffffffu, nn, j + 3);
            float4 f0 = feat4[(size_t)s0 * 32 + lane];
            float4 f1 = feat4[(size_t)s1 * 32 + lane];
            float4 f2 = feat4[(size_t)s2 * 32 + lane];
            float4 f3 = feat4[(size_t)s3 * 32 + lane];
            a0.x = fmaf(f0.x, n0, a0.x); a0.y = fmaf(f0.y, n0, a0.y);
            a0.z = fmaf(f0.z, n0, a0.z); a0.w = fmaf(f0.w, n0, a0.w);
            a1.x = fmaf(f1.x, n1, a1.x); a1.y = fmaf(f1.y, n1, a1.y);
            a1.z = fmaf(f1.z, n1, a1.z); a1.w = fmaf(f1.w, n1, a1.w);
            a2.x = fmaf(f2.x, n2, a2.x); a2.y = fmaf(f2.y, n2, a2.y);
            a2.z = fmaf(f2.z, n2, a2.z); a2.w = fmaf(f2.w, n2, a2.w);
            a3.x = fmaf(f3.x, n3, a3.x); a3.y = fmaf(f3.y, n3, a3.y);
            a3.z = fmaf(f3.z, n3, a3.z); a3.w = fmaf(f3.w, n3, a3.w);
        }
        for (; j < cn; j++) {
            int   s0 = __shfl_sync(0xffffffffu, sid, j);
            float n0 = __shfl_sync(0xffffffffu, nn, j);
            float4 f0 = feat4[(size_t)s0 * 32 + lane];
            a0.x = fmaf(f0.x, n0, a0.x); a0.y = fmaf(f0.y, n0, a0.y);
            a0.z = fmaf(f0.z, n0, a0.z); a0.w = fmaf(f0.w, n0, a0.w);
        }
    }

    float nd = __ldg(norm + row);
    float ox = (a0.x + a1.x + a2.x + a3.x) * nd;
    float oy = (a0.y + a1.y + a2.y + a3.y) * nd;
    float oz = (a0.z + a1.z + a2.z + a3.z) * nd;
    float ow = (a0.w + a1.w + a2.w + a3.w) * nd;

    __half2 h0 = __floats2half2_rn(ox, oy);
    __half2 h1 = __floats2half2_rn(oz, ow);
    uint2 u;
    u.x = *reinterpret_cast<unsigned*>(&h0);
    u.y = *reinterpret_cast<unsigned*>(&h1);
    reinterpret_cast<uint2*>(g_agg_h)[(size_t)row * 32 + lane] = u;
}

// ---------------------------------------------------------------------------
// K4: out = tanh(agg_h @ Wt_h + b) via single-pass fp16 WMMA (m16n16k16,
// fp32 accumulate). Block: 64 rows x 128 cols, 256 thr = 8 warps
// (4 row-warps x 2 col-warps); warp = 16 rows x 64 cols = 4 tiles.
// smem staging: As 64*136*2 + Bs 128*136*2 = 52,224B -> 4 CTA/SM.
// Epilogue: C frags -> smem fp32 (overlay) -> bias + tanh -> float4 stores.
// ---------------------------------------------------------------------------
__global__ void __launch_bounds__(256)
gemm_tanh_h_kernel(const float* __restrict__ bias_in,
                   float* __restrict__ out) {
    extern __shared__ __align__(16) char shraw[];
    __half* As = reinterpret_cast<__half*>(shraw);            // [GM][ALD]
    __half* Bs = As + GM * ALD;                               // [FDIM][ALD]

    const int t    = threadIdx.x;       // 0..255
    const int wid  = t >> 5;            // 0..7
    const int wr   = wid >> 1;          // row-warp 0..3 -> rows wr*16
    const int wc   = wid & 1;           // col-warp 0..1 -> cols wc*64
    const int row0 = blockIdx.x * GM;

    // stage Bs (Wt fp16): 128 rows x 32 uint2
    {
        uint2* Bs2 = reinterpret_cast<uint2*>(Bs);
        const uint2* Wt2 = reinterpret_cast<const uint2*>(g_Wt_h);
        #pragma unroll
        for (int i = t; i < FDIM * 32; i += 256) {
            int r = i >> 5, c8 = i & 31;
            Bs2[r * (ALD / 4) + c8] = Wt2[r * 32 + c8];
        }
    }
    // stage As (agg fp16): 64 rows x 32 uint2, zero-pad tail rows
    {
        uint2* As2 = reinterpret_cast<uint2*>(As);
        const uint2* agg2 = reinterpret_cast<const uint2*>(g_agg_h);
        #pragma unroll
        for (int i = t; i < GM * 32; i += 256) {
            int r = i >> 5, c8 = i & 31;
            int row = row0 + r;
            uint2 v = make_uint2(0u, 0u);
            if (row < N_NODES) v = agg2[(size_t)row * 32 + c8];
            As2[r * (ALD / 4) + c8] = v;
        }
    }
    __syncthreads();

    wmma::fragment<wmma::accumulator, 16, 16, 16, float> acc[4];
    #pragma unroll
    for (int c = 0; c < 4; c++) wmma::fill_fragment(acc[c], 0.0f);

    #pragma unroll
    for (int k = 0; k < FDIM / 16; k++) {
        wmma::fragment<wmma::matrix_a, 16, 16, 16, __half, wmma::row_major> af;
        wmma::load_matrix_sync(af, As + (wr * 16) * ALD + k * 16, ALD);
        #pragma unroll
        for (int c = 0; c < 4; c++) {
            wmma::fragment<wmma::matrix_b, 16, 16, 16, __half, wmma::row_major> bf;
            wmma::load_matrix_sync(bf, Bs + (k * 16) * ALD + wc * 64 + c * 16, ALD);
            wmma::mma_sync(acc[c], af, bf, acc[c]);
        }
    }

    __syncthreads();   // staging reads done; overlay smem as fp32 C buffer
    float* Cs = reinterpret_cast<float*>(shraw);              // [GM][CLD]
    #pragma unroll
    for (int c = 0; c < 4; c++)
        wmma::store_matrix_sync(Cs + (wr * 16) * CLD + wc * 64 + c * 16,
                                acc[c], CLD, wmma::mem_row_major);
    __syncthreads();

    // epilogue: bias + tanh + coalesced float4 store
    {
        const float4* b4 = reinterpret_cast<const float4*>(bias_in);
        #pragma unroll
        for (int i = t; i < GM * 32; i += 256) {
            int r = i >> 5, c4 = i & 31;
            int row = row0 + r;
            if (row < N_NODES) {
                float4 v = *reinterpret_cast<float4*>(Cs + r * CLD + c4 * 4);
                float4 bb = b4[c4];
                float4 o;
                o.x = tanhf(v.x + bb.x);
                o.y = tanhf(v.y + bb.y);
                o.z = tanhf(v.z + bb.z);
                o.w = tanhf(v.w + bb.w);
                reinterpret_cast<float4*>(out)[(size_t)row * 32 + c4] = o;
            }
        }
    }
}

// ---------------------------------------------------------------------------
// Launch. Inputs: features, norm, W, b, src, dst. Output float [N, 128].
// ---------------------------------------------------------------------------
extern "C" void kernel_launch(void* const* d_in, const int* in_sizes, int n_in,
                              void* d_out, int out_size) {
    const float* feat = (const float*)d_in[0];
    const float* norm = (const float*)d_in[1];
    const float* W    = (const float*)d_in[2];
    const float* b    = (const float*)d_in[3];
    const int*   src  = (const int*)d_in[4];
    const int*   dst  = (const int*)d_in[5];
    float* out = (float*)d_out;

    prep_kernel<<<(N_NODES + 255) / 256, 256>>>(W);
    build_lists_kernel<<<(N_EDGES + 255) / 256, 256>>>(src, dst);
    gather_kernel<<<(N_NODES + 7) / 8, 256>>>(feat, norm);

    int smem_stage = (GM + FDIM) * ALD * (int)sizeof(__half);   // 52,224 B
    int smem_epi   = GM * CLD * (int)sizeof(float);             // 33,792 B
    int smem = smem_stage > smem_epi ? smem_stage : smem_epi;
    cudaFuncSetAttribute(gemm_tanh_h_kernel,
                         cudaFuncAttributeMaxDynamicSharedMemorySize, smem);
    gemm_tanh_h_kernel<<<(N_NODES + GM - 1) / GM, 256, smem>>>(b, out);
}